// round 1
// baseline (speedup 1.0000x reference)
#include <cuda_runtime.h>

// ---------------------------------------------------------------------------
// Problem constants (fixed-shape problem)
// ---------------------------------------------------------------------------
#define NN 100000   // nodes
#define NE 800000   // edges
#define DHID 256
#define DOUT 128
#define NBLK 98     // ceil(NN/1024) for scan

// ---------------------------------------------------------------------------
// Device-global scratch (no runtime allocation allowed)
// ---------------------------------------------------------------------------
__device__ int   g_cnt[NN];
__device__ int   g_fill[NN];
__device__ int   g_rowptr[NN + 1];
__device__ int   g_bsum[128];
__device__ int   g_csrsrc[NE];
__device__ float g_dinv[NN];
__device__ float g_bufA[(size_t)NN * DHID];   // GEMM output
__device__ float g_bufB[(size_t)NN * DHID];   // aggregation output / GEMM input
__device__ float g_S[2];                      // LN sum, sumsq
__device__ float g_prm[2];                    // LN mean, scale

// ---------------------------------------------------------------------------
// CSR build
// ---------------------------------------------------------------------------
__global__ void k_zero_counts() {
    int i = blockIdx.x * blockDim.x + threadIdx.x;
    if (i < NN) { g_cnt[i] = 0; g_fill[i] = 0; }
}

__global__ void k_degree(const int* __restrict__ dst) {
    int e = blockIdx.x * blockDim.x + threadIdx.x;
    if (e < NE) atomicAdd(&g_cnt[dst[e]], 1);
}

__global__ void k_dinv() {
    int v = blockIdx.x * blockDim.x + threadIdx.x;
    if (v < NN) g_dinv[v] = rsqrtf((float)g_cnt[v] + 1.0f);
}

// Block-level exclusive scan (Hillis-Steele), 1024 elems per block
__global__ void k_scan1() {
    __shared__ int s[1024];
    int t = threadIdx.x;
    int i = blockIdx.x * 1024 + t;
    int v = (i < NN) ? g_cnt[i] : 0;
    s[t] = v;
    __syncthreads();
    for (int off = 1; off < 1024; off <<= 1) {
        int add = (t >= off) ? s[t - off] : 0;
        __syncthreads();
        s[t] += add;
        __syncthreads();
    }
    if (i < NN) g_rowptr[i] = s[t] - v;      // exclusive
    if (t == 1023) g_bsum[blockIdx.x] = s[1023];
}

__global__ void k_scan2() {
    int run = 0;
    for (int b = 0; b < NBLK; b++) {
        int x = g_bsum[b];
        g_bsum[b] = run;
        run += x;
    }
    g_rowptr[NN] = run;  // == NE
}

__global__ void k_scan3() {
    int i = blockIdx.x * blockDim.x + threadIdx.x;
    if (i < NN) g_rowptr[i] += g_bsum[i >> 10];
}

__global__ void k_scatter(const int* __restrict__ src, const int* __restrict__ dst) {
    int e = blockIdx.x * blockDim.x + threadIdx.x;
    if (e < NE) {
        int d = dst[e];
        int pos = g_rowptr[d] + atomicAdd(&g_fill[d], 1);
        g_csrsrc[pos] = src[e];
    }
}

// ---------------------------------------------------------------------------
// SGEMM: C[M,Nc] = A[M,256] @ W[256,Nc], 128x128 tile, BK=8, double-buffered
// ---------------------------------------------------------------------------
__global__ void __launch_bounds__(256, 2)
k_sgemm(const float* __restrict__ A, const float* __restrict__ W,
        float* __restrict__ C, int M, int Nc)
{
    const int K = 256;
    __shared__ float As[2][8][128];
    __shared__ float Bs[2][8][128];

    int tid = threadIdx.x;
    int bm = blockIdx.y * 128;
    int bn = blockIdx.x * 128;

    int aRow = tid >> 1;            // 0..127
    int aCol = (tid & 1) * 4;       // 0 or 4
    int bRow = tid >> 5;            // 0..7
    int bCol = (tid & 31) * 4;      // 0..124

    int ty = tid >> 4, tx = tid & 15;
    int rowBase = ty * 8, colBase = tx * 8;

    float acc[8][8];
#pragma unroll
    for (int i = 0; i < 8; i++)
#pragma unroll
        for (int j = 0; j < 8; j++) acc[i][j] = 0.f;

    float4 av, bv;
    {
        int gr = bm + aRow;
        av = (gr < M) ? *(const float4*)(A + (size_t)gr * K + aCol)
                      : make_float4(0.f, 0.f, 0.f, 0.f);
        bv = *(const float4*)(W + (size_t)bRow * Nc + bn + bCol);
    }
    As[0][aCol + 0][aRow] = av.x; As[0][aCol + 1][aRow] = av.y;
    As[0][aCol + 2][aRow] = av.z; As[0][aCol + 3][aRow] = av.w;
    *(float4*)&Bs[0][bRow][bCol] = bv;
    __syncthreads();

    const int nTiles = K / 8;  // 32
    for (int t = 0; t < nTiles; t++) {
        int cur = t & 1, nxt = cur ^ 1;
        if (t + 1 < nTiles) {
            int k0 = (t + 1) * 8;
            int gr = bm + aRow;
            av = (gr < M) ? *(const float4*)(A + (size_t)gr * K + k0 + aCol)
                          : make_float4(0.f, 0.f, 0.f, 0.f);
            bv = *(const float4*)(W + (size_t)(k0 + bRow) * Nc + bn + bCol);
        }
#pragma unroll
        for (int kk = 0; kk < 8; kk++) {
            float4 a0 = *(const float4*)&As[cur][kk][rowBase];
            float4 a1 = *(const float4*)&As[cur][kk][rowBase + 4];
            float4 b0 = *(const float4*)&Bs[cur][kk][colBase];
            float4 b1 = *(const float4*)&Bs[cur][kk][colBase + 4];
            float ar[8] = {a0.x, a0.y, a0.z, a0.w, a1.x, a1.y, a1.z, a1.w};
            float br[8] = {b0.x, b0.y, b0.z, b0.w, b1.x, b1.y, b1.z, b1.w};
#pragma unroll
            for (int i = 0; i < 8; i++)
#pragma unroll
                for (int j = 0; j < 8; j++)
                    acc[i][j] += ar[i] * br[j];
        }
        if (t + 1 < nTiles) {
            As[nxt][aCol + 0][aRow] = av.x; As[nxt][aCol + 1][aRow] = av.y;
            As[nxt][aCol + 2][aRow] = av.z; As[nxt][aCol + 3][aRow] = av.w;
            *(float4*)&Bs[nxt][bRow][bCol] = bv;
            __syncthreads();
        }
    }

#pragma unroll
    for (int i = 0; i < 8; i++) {
        int gr = bm + rowBase + i;
        if (gr < M) {
            float* cp = C + (size_t)gr * Nc + bn + colBase;
            *(float4*)cp       = make_float4(acc[i][0], acc[i][1], acc[i][2], acc[i][3]);
            *(float4*)(cp + 4) = make_float4(acc[i][4], acc[i][5], acc[i][6], acc[i][7]);
        }
    }
}

// ---------------------------------------------------------------------------
// Aggregation: out[v] = dinv[v]*(sum_e dinv[src]*h[src] + dinv[v]*h[v]) + bias
// One warp per node, D=256 (8 floats/lane). Optionally accumulates LN stats.
// ---------------------------------------------------------------------------
__global__ void k_agg256(const float* __restrict__ h, const float* __restrict__ bias,
                         float* __restrict__ out, int stats)
{
    int warp = threadIdx.x >> 5, lane = threadIdx.x & 31;
    int v = blockIdx.x * 8 + warp;   // grid is exactly NN/8 blocks

    float4 a0 = make_float4(0.f, 0.f, 0.f, 0.f);
    float4 a1 = make_float4(0.f, 0.f, 0.f, 0.f);

    int beg = g_rowptr[v], end = g_rowptr[v + 1];
    int nb = end - beg;
    for (int base = 0; base < nb; base += 32) {
        int rem = nb - base;
        int cnt = rem < 32 ? rem : 32;
        int idx = base + lane;
        int sl = (idx < nb) ? g_csrsrc[beg + idx] : 0;
        float wl = (idx < nb) ? g_dinv[sl] : 0.f;
        for (int j = 0; j < cnt; j++) {
            int   s = __shfl_sync(0xffffffffu, sl, j);
            float w = __shfl_sync(0xffffffffu, wl, j);
            const float4* r = (const float4*)(h + (size_t)s * 256);
            float4 f0 = r[lane], f1 = r[lane + 32];
            a0.x += w * f0.x; a0.y += w * f0.y; a0.z += w * f0.z; a0.w += w * f0.w;
            a1.x += w * f1.x; a1.y += w * f1.y; a1.z += w * f1.z; a1.w += w * f1.w;
        }
    }
    // self-loop + outer dinv[v] + bias
    float dv = g_dinv[v];
    {
        const float4* r = (const float4*)(h + (size_t)v * 256);
        float4 f0 = r[lane], f1 = r[lane + 32];
        a0.x += dv * f0.x; a0.y += dv * f0.y; a0.z += dv * f0.z; a0.w += dv * f0.w;
        a1.x += dv * f1.x; a1.y += dv * f1.y; a1.z += dv * f1.z; a1.w += dv * f1.w;
    }
    const float4* bb = (const float4*)bias;
    float4 b0 = bb[lane], b1 = bb[lane + 32];
    float4 r0, r1;
    r0.x = a0.x * dv + b0.x; r0.y = a0.y * dv + b0.y;
    r0.z = a0.z * dv + b0.z; r0.w = a0.w * dv + b0.w;
    r1.x = a1.x * dv + b1.x; r1.y = a1.y * dv + b1.y;
    r1.z = a1.z * dv + b1.z; r1.w = a1.w * dv + b1.w;

    float4* op = (float4*)(out + (size_t)v * 256);
    op[lane] = r0; op[lane + 32] = r1;

    if (stats) {
        float lsum = r0.x + r0.y + r0.z + r0.w + r1.x + r1.y + r1.z + r1.w;
        float lsq  = r0.x*r0.x + r0.y*r0.y + r0.z*r0.z + r0.w*r0.w
                   + r1.x*r1.x + r1.y*r1.y + r1.z*r1.z + r1.w*r1.w;
#pragma unroll
        for (int off = 16; off > 0; off >>= 1) {
            lsum += __shfl_down_sync(0xffffffffu, lsum, off);
            lsq  += __shfl_down_sync(0xffffffffu, lsq,  off);
        }
        __shared__ float ss[8], sq[8];
        if (lane == 0) { ss[warp] = lsum; sq[warp] = lsq; }
        __syncthreads();
        if (threadIdx.x == 0) {
            float S = 0.f, Q = 0.f;
#pragma unroll
            for (int w = 0; w < 8; w++) { S += ss[w]; Q += sq[w]; }
            atomicAdd(&g_S[0], S);
            atomicAdd(&g_S[1], Q);
        }
    }
}

// D=128 variant for the final layer (writes d_out, no stats)
__global__ void k_agg128(const float* __restrict__ h, const float* __restrict__ bias,
                         float* __restrict__ out)
{
    int warp = threadIdx.x >> 5, lane = threadIdx.x & 31;
    int v = blockIdx.x * 8 + warp;

    float4 a0 = make_float4(0.f, 0.f, 0.f, 0.f);
    int beg = g_rowptr[v], end = g_rowptr[v + 1];
    int nb = end - beg;
    for (int base = 0; base < nb; base += 32) {
        int rem = nb - base;
        int cnt = rem < 32 ? rem : 32;
        int idx = base + lane;
        int sl = (idx < nb) ? g_csrsrc[beg + idx] : 0;
        float wl = (idx < nb) ? g_dinv[sl] : 0.f;
        for (int j = 0; j < cnt; j++) {
            int   s = __shfl_sync(0xffffffffu, sl, j);
            float w = __shfl_sync(0xffffffffu, wl, j);
            const float4* r = (const float4*)(h + (size_t)s * 128);
            float4 f0 = r[lane];
            a0.x += w * f0.x; a0.y += w * f0.y; a0.z += w * f0.z; a0.w += w * f0.w;
        }
    }
    float dv = g_dinv[v];
    {
        const float4* r = (const float4*)(h + (size_t)v * 128);
        float4 f0 = r[lane];
        a0.x += dv * f0.x; a0.y += dv * f0.y; a0.z += dv * f0.z; a0.w += dv * f0.w;
    }
    const float4* bb = (const float4*)bias;
    float4 b0 = bb[lane];
    float4 r0;
    r0.x = a0.x * dv + b0.x; r0.y = a0.y * dv + b0.y;
    r0.z = a0.z * dv + b0.z; r0.w = a0.w * dv + b0.w;
    ((float4*)(out + (size_t)v * 128))[lane] = r0;
}

// ---------------------------------------------------------------------------
// LayerNorm(graph) helpers
// ---------------------------------------------------------------------------
__global__ void k_zeroS() { g_S[0] = 0.f; g_S[1] = 0.f; }

__global__ void k_lnfin() {
    float cnt = (float)NN * 256.0f;
    float mean = g_S[0] / cnt;
    float var  = g_S[1] / cnt - mean * mean;
    var = fmaxf(var, 0.f);
    g_prm[0] = mean;
    g_prm[1] = 1.0f / (sqrtf(var) + 1e-5f);
}

// in-place: y = lrelu((x - mean)*scale * gamma[c] + beta[c])
__global__ void k_apply(float* __restrict__ buf,
                        const float* __restrict__ gma,
                        const float* __restrict__ bta)
{
    int i4 = blockIdx.x * blockDim.x + threadIdx.x;  // exactly NN*256/4 threads
    float mean = g_prm[0], scale = g_prm[1];
    int c4 = i4 & 63;
    float4 g = ((const float4*)gma)[c4];
    float4 b = ((const float4*)bta)[c4];
    float4 v = ((float4*)buf)[i4];
    v.x = (v.x - mean) * scale * g.x + b.x;
    v.y = (v.y - mean) * scale * g.y + b.y;
    v.z = (v.z - mean) * scale * g.z + b.z;
    v.w = (v.w - mean) * scale * g.w + b.w;
    v.x = v.x > 0.f ? v.x : 0.01f * v.x;
    v.y = v.y > 0.f ? v.y : 0.01f * v.y;
    v.z = v.z > 0.f ? v.z : 0.01f * v.z;
    v.w = v.w > 0.f ? v.w : 0.01f * v.w;
    ((float4*)buf)[i4] = v;
}

// ---------------------------------------------------------------------------
// Host launcher
// ---------------------------------------------------------------------------
extern "C" void kernel_launch(void* const* d_in, const int* in_sizes, int n_in,
                              void* d_out, int out_size)
{
    const float* x   = (const float*)d_in[0];
    const int*   ei  = (const int*)d_in[1];
    const int*   src = ei;
    const int*   dst = ei + NE;
    const float* W1 = (const float*)d_in[2];
    const float* b1 = (const float*)d_in[3];
    const float* g1 = (const float*)d_in[4];
    const float* e1 = (const float*)d_in[5];
    const float* W2 = (const float*)d_in[6];
    const float* b2 = (const float*)d_in[7];
    const float* g2 = (const float*)d_in[8];
    const float* e2 = (const float*)d_in[9];
    const float* W3 = (const float*)d_in[10];
    const float* b3 = (const float*)d_in[11];
    const float* g3 = (const float*)d_in[12];
    const float* e3 = (const float*)d_in[13];
    const float* W4 = (const float*)d_in[14];
    const float* b4 = (const float*)d_in[15];
    float* out = (float*)d_out;

    float *bufA = nullptr, *bufB = nullptr;
    cudaGetSymbolAddress((void**)&bufA, g_bufA);
    cudaGetSymbolAddress((void**)&bufB, g_bufB);

    const int T = 256;
    // ---- degree + CSR (rebuilt every call; deterministic) ----
    k_zero_counts<<<(NN + T - 1) / T, T>>>();
    k_degree<<<(NE + T - 1) / T, T>>>(dst);
    k_dinv<<<(NN + T - 1) / T, T>>>();
    k_scan1<<<NBLK, 1024>>>();
    k_scan2<<<1, 1>>>();
    k_scan3<<<(NN + T - 1) / T, T>>>();
    k_scatter<<<(NE + T - 1) / T, T>>>(src, dst);

    dim3 gemmGrid(2, (NN + 127) / 128);   // 256-col GEMMs
    int aggBlocks = NN / 8;               // 12500
    int applyBlocks = (NN * 256 / 4) / T; // 25000

    // ---- layer 1 ----
    k_sgemm<<<gemmGrid, 256>>>(x, W1, bufA, NN, 256);
    k_zeroS<<<1, 1>>>();
    k_agg256<<<aggBlocks, 256>>>(bufA, b1, bufB, 1);
    k_lnfin<<<1, 1>>>();
    k_apply<<<applyBlocks, T>>>(bufB, g1, e1);

    // ---- layer 2 ----
    k_sgemm<<<gemmGrid, 256>>>(bufB, W2, bufA, NN, 256);
    k_zeroS<<<1, 1>>>();
    k_agg256<<<aggBlocks, 256>>>(bufA, b2, bufB, 1);
    k_lnfin<<<1, 1>>>();
    k_apply<<<applyBlocks, T>>>(bufB, g2, e2);

    // ---- layer 3 ----
    k_sgemm<<<gemmGrid, 256>>>(bufB, W3, bufA, NN, 256);
    k_zeroS<<<1, 1>>>();
    k_agg256<<<aggBlocks, 256>>>(bufA, b3, bufB, 1);
    k_lnfin<<<1, 1>>>();
    k_apply<<<applyBlocks, T>>>(bufB, g3, e3);

    // ---- layer 4 (D=128, no LN, writes d_out) ----
    k_sgemm<<<dim3(1, (NN + 127) / 128), 256>>>(bufB, W4, bufA, NN, 128);
    k_agg128<<<aggBlocks, 256>>>(bufA, b4, out);
}

// round 5
// speedup vs baseline: 1.4200x; 1.4200x over previous
#include <cuda_runtime.h>
#include <cuda_bf16.h>
#include <cstdint>

// ---------------------------------------------------------------------------
// Problem constants
// ---------------------------------------------------------------------------
#define NN 100000   // nodes
#define NE 800000   // edges
#define NBLK 98     // ceil(NN/1024) for scan

// ---------------------------------------------------------------------------
// Device-global scratch
// ---------------------------------------------------------------------------
__device__ int   g_cnt[NN];
__device__ int   g_fill[NN];
__device__ int   g_rowptr[NN + 1];
__device__ int   g_bsum[128];
__device__ int   g_csrsrc[NE];
__device__ float g_dinv[NN];
__device__ __align__(16) float g_bufA[(size_t)NN * 256];
__device__ __align__(16) float g_bufB[(size_t)NN * 256];
__device__ float g_S[2];
__device__ float g_prm[2];

// Transposed ([n][k]) bf16 hi/lo weight images
__device__ __align__(16) __nv_bfloat16 g_w1h[256 * 256], g_w1l[256 * 256];
__device__ __align__(16) __nv_bfloat16 g_w2h[256 * 256], g_w2l[256 * 256];
__device__ __align__(16) __nv_bfloat16 g_w3h[256 * 256], g_w3l[256 * 256];
__device__ __align__(16) __nv_bfloat16 g_w4h[128 * 256], g_w4l[128 * 256];

static __device__ __forceinline__ uint32_t smem_to_u32(const void* p) {
    uint32_t a;
    asm("{ .reg .u64 t; cvta.to.shared.u64 t, %1; cvt.u32.u64 %0, t; }" : "=r"(a) : "l"(p));
    return a;
}

#define LDMX4(r0, r1, r2, r3, addr) \
    asm volatile("ldmatrix.sync.aligned.m8n8.x4.shared.b16 {%0,%1,%2,%3}, [%4];" \
                 : "=r"(r0), "=r"(r1), "=r"(r2), "=r"(r3) : "r"(addr))

#define MMA16816(d, a, b) \
    asm volatile("mma.sync.aligned.m16n8k16.row.col.f32.bf16.bf16.f32 " \
                 "{%0,%1,%2,%3}, {%4,%5,%6,%7}, {%8,%9}, {%0,%1,%2,%3};" \
                 : "+f"((d)[0]), "+f"((d)[1]), "+f"((d)[2]), "+f"((d)[3]) \
                 : "r"((a)[0]), "r"((a)[1]), "r"((a)[2]), "r"((a)[3]), \
                   "r"((b)[0]), "r"((b)[1]))

static __device__ __forceinline__ uint32_t packbf2(float a, float b) {
    __nv_bfloat162 t = __floats2bfloat162_rn(a, b);
    return *reinterpret_cast<uint32_t*>(&t);
}

// ---------------------------------------------------------------------------
// CSR build
// ---------------------------------------------------------------------------
__global__ void k_zero_counts() {
    int i = blockIdx.x * blockDim.x + threadIdx.x;
    if (i < NN) { g_cnt[i] = 0; g_fill[i] = 0; }
}
__global__ void k_degree(const int* __restrict__ dst) {
    int e = blockIdx.x * blockDim.x + threadIdx.x;
    if (e < NE) atomicAdd(&g_cnt[dst[e]], 1);
}
__global__ void k_dinv() {
    int v = blockIdx.x * blockDim.x + threadIdx.x;
    if (v < NN) g_dinv[v] = rsqrtf((float)g_cnt[v] + 1.0f);
}
__global__ void k_scan1() {
    __shared__ int s[1024];
    int t = threadIdx.x;
    int i = blockIdx.x * 1024 + t;
    int v = (i < NN) ? g_cnt[i] : 0;
    s[t] = v;
    __syncthreads();
    for (int off = 1; off < 1024; off <<= 1) {
        int add = (t >= off) ? s[t - off] : 0;
        __syncthreads();
        s[t] += add;
        __syncthreads();
    }
    if (i < NN) g_rowptr[i] = s[t] - v;
    if (t == 1023) g_bsum[blockIdx.x] = s[1023];
}
__global__ void k_scan2() {
    int run = 0;
    for (int b = 0; b < NBLK; b++) { int x = g_bsum[b]; g_bsum[b] = run; run += x; }
    g_rowptr[NN] = run;
}
__global__ void k_scan3() {
    int i = blockIdx.x * blockDim.x + threadIdx.x;
    if (i < NN) g_rowptr[i] += g_bsum[i >> 10];
}
__global__ void k_scatter(const int* __restrict__ src, const int* __restrict__ dst) {
    int e = blockIdx.x * blockDim.x + threadIdx.x;
    if (e < NE) {
        int d = dst[e];
        int pos = g_rowptr[d] + atomicAdd(&g_fill[d], 1);
        g_csrsrc[pos] = src[e];
    }
}

// ---------------------------------------------------------------------------
// Weight prep: W[k][n] fp32 -> transposed [n][k] bf16 hi/lo
// ---------------------------------------------------------------------------
__global__ void k_wprep(const float* __restrict__ W, __nv_bfloat16* __restrict__ hi,
                        __nv_bfloat16* __restrict__ lo, int Nc) {
    int i = blockIdx.x * blockDim.x + threadIdx.x;
    if (i >= 256 * Nc) return;
    int k = i / Nc, n = i - k * Nc;
    float w = W[i];
    __nv_bfloat16 h = __float2bfloat16_rn(w);
    float rem = w - __bfloat162float(h);
    __nv_bfloat16 l = __float2bfloat16_rn(rem);
    int o = n * 256 + k;
    hi[o] = h;
    lo[o] = l;
}

// ---------------------------------------------------------------------------
// bf16-split HMMA GEMM: C[M,NC] = A[M,256] @ W[256,NC]
// CTA: 128x64 tile, 8 warps (4 m x 2 n), warp tile 32x32, BK=32.
// Terms: ah*wh + ah*wl + al*wh, fp32 accumulate.
// smem: A hi/lo 128x(32 bf16, 80B stride) ; W hi/lo 64x(32 bf16, 80B stride)
// 80B row stride => ldmatrix conflict-free (20*r mod 32 is a permutation).
// ---------------------------------------------------------------------------
#define OFF_AH 0
#define OFF_AL 10240
#define OFF_WH 20480
#define OFF_WL 25600
#define GEMM_SMEM 34816   // max(30720 tiles, 128*68*4 output staging)

template <int NC>
__global__ void __launch_bounds__(256, 2)
k_gemm_mma(const float* __restrict__ A,
           const __nv_bfloat16* __restrict__ Whi,
           const __nv_bfloat16* __restrict__ Wlo,
           float* __restrict__ C, int M)
{
    extern __shared__ __align__(16) char smem[];
    uint32_t sb = smem_to_u32(smem);

    int tid = threadIdx.x;
    int wid = tid >> 5, lane = tid & 31;
    int m0 = blockIdx.x * 128;
    int bn = blockIdx.y * 64;
    int warp_m = wid & 3;        // 0..3 -> rows warp_m*32
    int warp_n = wid >> 2;       // 0..1 -> cols warp_n*32

    float acc[2][4][4];
#pragma unroll
    for (int i = 0; i < 2; i++)
#pragma unroll
        for (int j = 0; j < 4; j++)
#pragma unroll
            for (int q = 0; q < 4; q++) acc[i][j][q] = 0.f;

    // A loader mapping: thread -> row tid/2, half tid&1 (4 float4 each chunk)
    int lrow = tid >> 1, lq = tid & 1;
    bool rowok = (m0 + lrow) < M;
    const float4* arow = (const float4*)(A + (size_t)(m0 + lrow) * 256);
    // W loader mapping: thread -> n-row tid/4, int4 idx tid&3 (1 int4 per tile)
    int wr = tid >> 2, wj = tid & 3;
    const int4* whrow = (const int4*)(Whi + (size_t)(bn + wr) * 256);
    const int4* wlrow = (const int4*)(Wlo + (size_t)(bn + wr) * 256);

    // ldmatrix base addresses (per-thread, without k-chunk/step offset)
    uint32_t aAddr[2], lAddr[2];
#pragma unroll
    for (int i = 0; i < 2; i++) {
        uint32_t row = warp_m * 32 + i * 16 + (lane & 15);
        uint32_t col = ((lane >> 4) & 1) * 16;
        aAddr[i] = sb + OFF_AH + row * 80 + col;
        lAddr[i] = sb + OFF_AL + row * 80 + col;
    }
    uint32_t bAddr[2], blAddr[2];
#pragma unroll
    for (int p = 0; p < 2; p++) {
        uint32_t row = warp_n * 32 + p * 16 + (lane & 7) + ((lane >> 4) & 1) * 8;
        uint32_t col = ((lane >> 3) & 1) * 16;
        bAddr[p]  = sb + OFF_WH + row * 80 + col;
        blAddr[p] = sb + OFF_WL + row * 80 + col;
    }

    for (int kc = 0; kc < 8; kc++) {
        // ---- A chunk: fp32 load, bf16 hi/lo split, store to smem ----
#pragma unroll
        for (int i = 0; i < 4; i++) {
            int f4 = lq * 4 + i;
            float4 v = rowok ? arow[kc * 8 + f4] : make_float4(0.f, 0.f, 0.f, 0.f);
            __nv_bfloat16 h0 = __float2bfloat16_rn(v.x), h1 = __float2bfloat16_rn(v.y);
            __nv_bfloat16 h2 = __float2bfloat16_rn(v.z), h3 = __float2bfloat16_rn(v.w);
            float l0 = v.x - __bfloat162float(h0), l1 = v.y - __bfloat162float(h1);
            float l2 = v.z - __bfloat162float(h2), l3 = v.w - __bfloat162float(h3);
            __nv_bfloat162 hh01; hh01.x = h0; hh01.y = h1;
            __nv_bfloat162 hh23; hh23.x = h2; hh23.y = h3;
            uint2 hv = make_uint2(*reinterpret_cast<uint32_t*>(&hh01),
                                  *reinterpret_cast<uint32_t*>(&hh23));
            uint2 lv = make_uint2(packbf2(l0, l1), packbf2(l2, l3));
            *(uint2*)(smem + OFF_AH + lrow * 80 + f4 * 8) = hv;
            *(uint2*)(smem + OFF_AL + lrow * 80 + f4 * 8) = lv;
        }
        // ---- W chunk: straight int4 copy ----
        *(int4*)(smem + OFF_WH + wr * 80 + wj * 16) = whrow[kc * 4 + wj];
        *(int4*)(smem + OFF_WL + wr * 80 + wj * 16) = wlrow[kc * 4 + wj];
        __syncthreads();

#pragma unroll
        for (int s = 0; s < 2; s++) {
            uint32_t ah[2][4], al[2][4];
            uint32_t wh[4][2], wl[4][2];
#pragma unroll
            for (int i = 0; i < 2; i++) {
                LDMX4(ah[i][0], ah[i][1], ah[i][2], ah[i][3], aAddr[i] + s * 32);
                LDMX4(al[i][0], al[i][1], al[i][2], al[i][3], lAddr[i] + s * 32);
            }
#pragma unroll
            for (int p = 0; p < 2; p++) {
                LDMX4(wh[2 * p][0], wh[2 * p][1], wh[2 * p + 1][0], wh[2 * p + 1][1],
                      bAddr[p] + s * 32);
                LDMX4(wl[2 * p][0], wl[2 * p][1], wl[2 * p + 1][0], wl[2 * p + 1][1],
                      blAddr[p] + s * 32);
            }
#pragma unroll
            for (int i = 0; i < 2; i++)
#pragma unroll
                for (int j = 0; j < 4; j++) {
                    MMA16816(acc[i][j], ah[i], wh[j]);
                    MMA16816(acc[i][j], ah[i], wl[j]);
                    MMA16816(acc[i][j], al[i], wh[j]);
                }
        }
        __syncthreads();
    }

    // ---- epilogue: stage 128x64 fp32 tile in smem (stride 68 floats) ----
    float* otile = (float*)smem;
#pragma unroll
    for (int i = 0; i < 2; i++)
#pragma unroll
        for (int j = 0; j < 4; j++) {
            int r0 = warp_m * 32 + i * 16 + (lane >> 2);
            int c0 = warp_n * 32 + j * 8 + (lane & 3) * 2;
            *(float2*)(otile + r0 * 68 + c0)       = make_float2(acc[i][j][0], acc[i][j][1]);
            *(float2*)(otile + (r0 + 8) * 68 + c0) = make_float2(acc[i][j][2], acc[i][j][3]);
        }
    __syncthreads();

#pragma unroll
    for (int it = 0; it < 8; it++) {
        int idx = tid + it * 256;     // 0..2047 float4 slots
        int row = idx >> 4;
        int c4 = idx & 15;
        int gr = m0 + row;
        if (gr < M) {
            float4 v = *(float4*)(otile + row * 68 + c4 * 4);
            *(float4*)(C + (size_t)gr * NC + bn + c4 * 4) = v;
        }
    }
}

// ---------------------------------------------------------------------------
// Aggregation (unchanged, proven correct)
// ---------------------------------------------------------------------------
__global__ void k_agg256(const float* __restrict__ h, const float* __restrict__ bias,
                         float* __restrict__ out, int stats)
{
    int warp = threadIdx.x >> 5, lane = threadIdx.x & 31;
    int v = blockIdx.x * 8 + warp;

    float4 a0 = make_float4(0.f, 0.f, 0.f, 0.f);
    float4 a1 = make_float4(0.f, 0.f, 0.f, 0.f);

    int beg = g_rowptr[v], end = g_rowptr[v + 1];
    int nb = end - beg;
    for (int base = 0; base < nb; base += 32) {
        int rem = nb - base;
        int cnt = rem < 32 ? rem : 32;
        int idx = base + lane;
        int sl = (idx < nb) ? g_csrsrc[beg + idx] : 0;
        float wl = (idx < nb) ? g_dinv[sl] : 0.f;
        for (int j = 0; j < cnt; j++) {
            int   s = __shfl_sync(0xffffffffu, sl, j);
            float w = __shfl_sync(0xffffffffu, wl, j);
            const float4* rr = (const float4*)(h + (size_t)s * 256);
            float4 f0 = rr[lane], f1 = rr[lane + 32];
            a0.x += w * f0.x; a0.y += w * f0.y; a0.z += w * f0.z; a0.w += w * f0.w;
            a1.x += w * f1.x; a1.y += w * f1.y; a1.z += w * f1.z; a1.w += w * f1.w;
        }
    }
    float dv = g_dinv[v];
    {
        const float4* rr = (const float4*)(h + (size_t)v * 256);
        float4 f0 = rr[lane], f1 = rr[lane + 32];
        a0.x += dv * f0.x; a0.y += dv * f0.y; a0.z += dv * f0.z; a0.w += dv * f0.w;
        a1.x += dv * f1.x; a1.y += dv * f1.y; a1.z += dv * f1.z; a1.w += dv * f1.w;
    }
    const float4* bb = (const float4*)bias;
    float4 b0 = bb[lane], b1 = bb[lane + 32];
    float4 r0, r1;
    r0.x = a0.x * dv + b0.x; r0.y = a0.y * dv + b0.y;
    r0.z = a0.z * dv + b0.z; r0.w = a0.w * dv + b0.w;
    r1.x = a1.x * dv + b1.x; r1.y = a1.y * dv + b1.y;
    r1.z = a1.z * dv + b1.z; r1.w = a1.w * dv + b1.w;

    float4* op = (float4*)(out + (size_t)v * 256);
    op[lane] = r0; op[lane + 32] = r1;

    if (stats) {
        float lsum = r0.x + r0.y + r0.z + r0.w + r1.x + r1.y + r1.z + r1.w;
        float lsq  = r0.x*r0.x + r0.y*r0.y + r0.z*r0.z + r0.w*r0.w
                   + r1.x*r1.x + r1.y*r1.y + r1.z*r1.z + r1.w*r1.w;
#pragma unroll
        for (int off = 16; off > 0; off >>= 1) {
            lsum += __shfl_down_sync(0xffffffffu, lsum, off);
            lsq  += __shfl_down_sync(0xffffffffu, lsq,  off);
        }
        __shared__ float ss[8], sq[8];
        if (lane == 0) { ss[warp] = lsum; sq[warp] = lsq; }
        __syncthreads();
        if (threadIdx.x == 0) {
            float S = 0.f, Q = 0.f;
#pragma unroll
            for (int w = 0; w < 8; w++) { S += ss[w]; Q += sq[w]; }
            atomicAdd(&g_S[0], S);
            atomicAdd(&g_S[1], Q);
        }
    }
}

__global__ void k_agg128(const float* __restrict__ h, const float* __restrict__ bias,
                         float* __restrict__ out)
{
    int warp = threadIdx.x >> 5, lane = threadIdx.x & 31;
    int v = blockIdx.x * 8 + warp;

    float4 a0 = make_float4(0.f, 0.f, 0.f, 0.f);
    int beg = g_rowptr[v], end = g_rowptr[v + 1];
    int nb = end - beg;
    for (int base = 0; base < nb; base += 32) {
        int rem = nb - base;
        int cnt = rem < 32 ? rem : 32;
        int idx = base + lane;
        int sl = (idx < nb) ? g_csrsrc[beg + idx] : 0;
        float wl = (idx < nb) ? g_dinv[sl] : 0.f;
        for (int j = 0; j < cnt; j++) {
            int   s = __shfl_sync(0xffffffffu, sl, j);
            float w = __shfl_sync(0xffffffffu, wl, j);
            const float4* rr = (const float4*)(h + (size_t)s * 128);
            float4 f0 = rr[lane];
            a0.x += w * f0.x; a0.y += w * f0.y; a0.z += w * f0.z; a0.w += w * f0.w;
        }
    }
    float dv = g_dinv[v];
    {
        const float4* rr = (const float4*)(h + (size_t)v * 128);
        float4 f0 = rr[lane];
        a0.x += dv * f0.x; a0.y += dv * f0.y; a0.z += dv * f0.z; a0.w += dv * f0.w;
    }
    const float4* bb = (const float4*)bias;
    float4 b0 = bb[lane];
    float4 r0;
    r0.x = a0.x * dv + b0.x; r0.y = a0.y * dv + b0.y;
    r0.z = a0.z * dv + b0.z; r0.w = a0.w * dv + b0.w;
    ((float4*)(out + (size_t)v * 128))[lane] = r0;
}

// ---------------------------------------------------------------------------
// LayerNorm(graph)
// ---------------------------------------------------------------------------
__global__ void k_zeroS() { g_S[0] = 0.f; g_S[1] = 0.f; }

__global__ void k_lnfin() {
    float cnt = (float)NN * 256.0f;
    float mean = g_S[0] / cnt;
    float var  = g_S[1] / cnt - mean * mean;
    var = fmaxf(var, 0.f);
    g_prm[0] = mean;
    g_prm[1] = 1.0f / (sqrtf(var) + 1e-5f);
}

__global__ void k_apply(float* __restrict__ buf,
                        const float* __restrict__ gma,
                        const float* __restrict__ bta)
{
    int i4 = blockIdx.x * blockDim.x + threadIdx.x;
    float mean = g_prm[0], scale = g_prm[1];
    int c4 = i4 & 63;
    float4 g = ((const float4*)gma)[c4];
    float4 b = ((const float4*)bta)[c4];
    float4 v = ((float4*)buf)[i4];
    v.x = (v.x - mean) * scale * g.x + b.x;
    v.y = (v.y - mean) * scale * g.y + b.y;
    v.z = (v.z - mean) * scale * g.z + b.z;
    v.w = (v.w - mean) * scale * g.w + b.w;
    v.x = v.x > 0.f ? v.x : 0.01f * v.x;
    v.y = v.y > 0.f ? v.y : 0.01f * v.y;
    v.z = v.z > 0.f ? v.z : 0.01f * v.z;
    v.w = v.w > 0.f ? v.w : 0.01f * v.w;
    ((float4*)buf)[i4] = v;
}

// ---------------------------------------------------------------------------
// Host launcher
// ---------------------------------------------------------------------------
extern "C" void kernel_launch(void* const* d_in, const int* in_sizes, int n_in,
                              void* d_out, int out_size)
{
    const float* x   = (const float*)d_in[0];
    const int*   ei  = (const int*)d_in[1];
    const int*   src = ei;
    const int*   dst = ei + NE;
    const float* W1 = (const float*)d_in[2];
    const float* b1 = (const float*)d_in[3];
    const float* g1 = (const float*)d_in[4];
    const float* e1 = (const float*)d_in[5];
    const float* W2 = (const float*)d_in[6];
    const float* b2 = (const float*)d_in[7];
    const float* g2 = (const float*)d_in[8];
    const float* e2 = (const float*)d_in[9];
    const float* W3 = (const float*)d_in[10];
    const float* b3 = (const float*)d_in[11];
    const float* g3 = (const float*)d_in[12];
    const float* e3 = (const float*)d_in[13];
    const float* W4 = (const float*)d_in[14];
    const float* b4 = (const float*)d_in[15];
    float* out = (float*)d_out;

    float *bufA = nullptr, *bufB = nullptr;
    cudaGetSymbolAddress((void**)&bufA, g_bufA);
    cudaGetSymbolAddress((void**)&bufB, g_bufB);
    __nv_bfloat16 *w1h, *w1l, *w2h, *w2l, *w3h, *w3l, *w4h, *w4l;
    cudaGetSymbolAddress((void**)&w1h, g_w1h); cudaGetSymbolAddress((void**)&w1l, g_w1l);
    cudaGetSymbolAddress((void**)&w2h, g_w2h); cudaGetSymbolAddress((void**)&w2l, g_w2l);
    cudaGetSymbolAddress((void**)&w3h, g_w3h); cudaGetSymbolAddress((void**)&w3l, g_w3l);
    cudaGetSymbolAddress((void**)&w4h, g_w4h); cudaGetSymbolAddress((void**)&w4l, g_w4l);

    const int T = 256;
    // ---- CSR build ----
    k_zero_counts<<<(NN + T - 1) / T, T>>>();
    k_degree<<<(NE + T - 1) / T, T>>>(dst);
    k_dinv<<<(NN + T - 1) / T, T>>>();
    k_scan1<<<NBLK, 1024>>>();
    k_scan2<<<1, 1>>>();
    k_scan3<<<(NN + T - 1) / T, T>>>();
    k_scatter<<<(NE + T - 1) / T, T>>>(src, dst);

    // ---- weight prep ----
    k_wprep<<<(256 * 256 + T - 1) / T, T>>>(W1, w1h, w1l, 256);
    k_wprep<<<(256 * 256 + T - 1) / T, T>>>(W2, w2h, w2l, 256);
    k_wprep<<<(256 * 256 + T - 1) / T, T>>>(W3, w3h, w3l, 256);
    k_wprep<<<(256 * 128 + T - 1) / T, T>>>(W4, w4h, w4l, 128);

    dim3 grid256((NN + 127) / 128, 4);   // 782 x 4 (BN=64)
    dim3 grid128((NN + 127) / 128, 2);   // 782 x 2
    int aggBlocks = NN / 8;               // 12500
    int applyBlocks = (NN * 256 / 4) / T; // 25000

    // ---- layer 1 ----
    k_gemm_mma<256><<<grid256, 256, GEMM_SMEM>>>(x, w1h, w1l, bufA, NN);
    k_zeroS<<<1, 1>>>();
    k_agg256<<<aggBlocks, 256>>>(bufA, b1, bufB, 1);
    k_lnfin<<<1, 1>>>();
    k_apply<<<applyBlocks, T>>>(bufB, g1, e1);

    // ---- layer 2 ----
    k_gemm_mma<256><<<grid256, 256, GEMM_SMEM>>>(bufB, w2h, w2l, bufA, NN);
    k_zeroS<<<1, 1>>>();
    k_agg256<<<aggBlocks, 256>>>(bufA, b2, bufB, 1);
    k_lnfin<<<1, 1>>>();
    k_apply<<<applyBlocks, T>>>(bufB, g2, e2);

    // ---- layer 3 ----
    k_gemm_mma<256><<<grid256, 256, GEMM_SMEM>>>(bufB, w3h, w3l, bufA, NN);
    k_zeroS<<<1, 1>>>();
    k_agg256<<<aggBlocks, 256>>>(bufA, b3, bufB, 1);
    k_lnfin<<<1, 1>>>();
    k_apply<<<applyBlocks, T>>>(bufB, g3, e3);

    // ---- layer 4 (D=128, no LN) ----
    k_gemm_mma<128><<<grid128, 256, GEMM_SMEM>>>(bufB, w4h, w4l, bufA, NN);
    k_agg128<<<aggBlocks, 256>>>(bufA, b4, out);
}

// round 6
// speedup vs baseline: 1.6087x; 1.1329x over previous
#include <cuda_runtime.h>
#include <cuda_bf16.h>
#include <cstdint>

// ---------------------------------------------------------------------------
// Problem constants
// ---------------------------------------------------------------------------
#define NN 100000   // nodes
#define NE 800000   // edges
#define NBLK 98     // ceil(NN/1024) for scan

// ---------------------------------------------------------------------------
// Device-global scratch
// ---------------------------------------------------------------------------
__device__ int   g_cnt[NN];
__device__ int   g_fill[NN];
__device__ int   g_rowptr[NN + 1];
__device__ int   g_bsum[128];
__device__ int   g_csrsrc[NE];
__device__ float g_dinv[NN];
__device__ __align__(16) float g_bufA[(size_t)NN * 256];   // GEMM out / agg in
__device__ __align__(16) float g_bufB[(size_t)NN * 256];   // agg out / apply in
__device__ __align__(16) __nv_bfloat16 g_ah[(size_t)NN * 256];  // GEMM A hi
__device__ __align__(16) __nv_bfloat16 g_al[(size_t)NN * 256];  // GEMM A lo
__device__ float g_S[2];
__device__ float g_prm[2];

// Transposed ([n][k]) bf16 hi/lo weight images
__device__ __align__(16) __nv_bfloat16 g_w1h[256 * 256], g_w1l[256 * 256];
__device__ __align__(16) __nv_bfloat16 g_w2h[256 * 256], g_w2l[256 * 256];
__device__ __align__(16) __nv_bfloat16 g_w3h[256 * 256], g_w3l[256 * 256];
__device__ __align__(16) __nv_bfloat16 g_w4h[128 * 256], g_w4l[128 * 256];

static __device__ __forceinline__ uint32_t smem_to_u32(const void* p) {
    uint32_t a;
    asm("{ .reg .u64 t; cvta.to.shared.u64 t, %1; cvt.u32.u64 %0, t; }" : "=r"(a) : "l"(p));
    return a;
}

#define LDMX4(r0, r1, r2, r3, addr) \
    asm volatile("ldmatrix.sync.aligned.m8n8.x4.shared.b16 {%0,%1,%2,%3}, [%4];" \
                 : "=r"(r0), "=r"(r1), "=r"(r2), "=r"(r3) : "r"(addr))

#define MMA16816(d, a, b) \
    asm volatile("mma.sync.aligned.m16n8k16.row.col.f32.bf16.bf16.f32 " \
                 "{%0,%1,%2,%3}, {%4,%5,%6,%7}, {%8,%9}, {%0,%1,%2,%3};" \
                 : "+f"((d)[0]), "+f"((d)[1]), "+f"((d)[2]), "+f"((d)[3]) \
                 : "r"((a)[0]), "r"((a)[1]), "r"((a)[2]), "r"((a)[3]), \
                   "r"((b)[0]), "r"((b)[1]))

#define CP_ASYNC16(saddr, gptr) \
    asm volatile("cp.async.cg.shared.global [%0], [%1], 16;" :: "r"(saddr), "l"(gptr))
#define CP_COMMIT() asm volatile("cp.async.commit_group;")
#define CP_WAIT1()  asm volatile("cp.async.wait_group 1;")
#define CP_WAIT0()  asm volatile("cp.async.wait_group 0;")

static __device__ __forceinline__ uint32_t packbf2(float a, float b) {
    __nv_bfloat162 t = __floats2bfloat162_rn(a, b);
    return *reinterpret_cast<uint32_t*>(&t);
}

// split a float4 into bf16-hi (uint2) and bf16-lo (uint2)
static __device__ __forceinline__ void split4(float4 v, uint2& hv, uint2& lv) {
    __nv_bfloat16 h0 = __float2bfloat16_rn(v.x), h1 = __float2bfloat16_rn(v.y);
    __nv_bfloat16 h2 = __float2bfloat16_rn(v.z), h3 = __float2bfloat16_rn(v.w);
    float l0 = v.x - __bfloat162float(h0), l1 = v.y - __bfloat162float(h1);
    float l2 = v.z - __bfloat162float(h2), l3 = v.w - __bfloat162float(h3);
    __nv_bfloat162 hh01; hh01.x = h0; hh01.y = h1;
    __nv_bfloat162 hh23; hh23.x = h2; hh23.y = h3;
    hv = make_uint2(*reinterpret_cast<uint32_t*>(&hh01),
                    *reinterpret_cast<uint32_t*>(&hh23));
    lv = make_uint2(packbf2(l0, l1), packbf2(l2, l3));
}

// ---------------------------------------------------------------------------
// CSR build
// ---------------------------------------------------------------------------
__global__ void k_zero_counts() {
    int i = blockIdx.x * blockDim.x + threadIdx.x;
    if (i < NN) { g_cnt[i] = 0; g_fill[i] = 0; }
}
__global__ void k_degree(const int* __restrict__ dst) {
    int e = blockIdx.x * blockDim.x + threadIdx.x;
    if (e < NE) atomicAdd(&g_cnt[dst[e]], 1);
}
__global__ void k_dinv() {
    int v = blockIdx.x * blockDim.x + threadIdx.x;
    if (v < NN) g_dinv[v] = rsqrtf((float)g_cnt[v] + 1.0f);
}
__global__ void k_scan1() {
    __shared__ int s[1024];
    int t = threadIdx.x;
    int i = blockIdx.x * 1024 + t;
    int v = (i < NN) ? g_cnt[i] : 0;
    s[t] = v;
    __syncthreads();
    for (int off = 1; off < 1024; off <<= 1) {
        int add = (t >= off) ? s[t - off] : 0;
        __syncthreads();
        s[t] += add;
        __syncthreads();
    }
    if (i < NN) g_rowptr[i] = s[t] - v;
    if (t == 1023) g_bsum[blockIdx.x] = s[1023];
}
__global__ void k_scan2() {
    int run = 0;
    for (int b = 0; b < NBLK; b++) { int x = g_bsum[b]; g_bsum[b] = run; run += x; }
    g_rowptr[NN] = run;
}
__global__ void k_scan3() {
    int i = blockIdx.x * blockDim.x + threadIdx.x;
    if (i < NN) g_rowptr[i] += g_bsum[i >> 10];
}
__global__ void k_scatter(const int* __restrict__ src, const int* __restrict__ dst) {
    int e = blockIdx.x * blockDim.x + threadIdx.x;
    if (e < NE) {
        int d = dst[e];
        int pos = g_rowptr[d] + atomicAdd(&g_fill[d], 1);
        g_csrsrc[pos] = src[e];
    }
}

// ---------------------------------------------------------------------------
// Weight prep: W[k][n] fp32 -> transposed [n][k] bf16 hi/lo
// ---------------------------------------------------------------------------
__global__ void k_wprep(const float* __restrict__ W, __nv_bfloat16* __restrict__ hi,
                        __nv_bfloat16* __restrict__ lo, int Nc) {
    int i = blockIdx.x * blockDim.x + threadIdx.x;
    if (i >= 256 * Nc) return;
    int k = i / Nc, n = i - k * Nc;
    float w = W[i];
    __nv_bfloat16 h = __float2bfloat16_rn(w);
    float rem = w - __bfloat162float(h);
    __nv_bfloat16 l = __float2bfloat16_rn(rem);
    int o = n * 256 + k;
    hi[o] = h;
    lo[o] = l;
}

// X conversion (layer-1 input): fp32 -> bf16 hi/lo images
__global__ void k_xconv(const float* __restrict__ x,
                        __nv_bfloat16* __restrict__ ah, __nv_bfloat16* __restrict__ al) {
    int i4 = blockIdx.x * blockDim.x + threadIdx.x;  // NN*64 total
    float4 v = ((const float4*)x)[i4];
    uint2 hv, lv;
    split4(v, hv, lv);
    ((uint2*)ah)[i4] = hv;
    ((uint2*)al)[i4] = lv;
}

// ---------------------------------------------------------------------------
// bf16-split HMMA GEMM: C[M,NC] = A[M,256] @ W[256,NC]
// A pre-converted to bf16 hi/lo. CTA 128x64, 8 warps (4m x 2n), BK=32,
// 2-stage cp.async pipeline. Terms ah*wh + ah*wl + al*wh, fp32 accumulate.
// smem/stage: AH 128x80B, AL 128x80B, WH 64x80B, WL 64x80B = 30720 B.
// ---------------------------------------------------------------------------
#define ST_AH 0
#define ST_AL 10240
#define ST_WH 20480
#define ST_WL 25600
#define STAGE_SZ 30720
#define GEMM_SMEM (2 * STAGE_SZ)   // 61440 >= 34816 output staging

template <int NC>
__global__ void __launch_bounds__(256, 2)
k_gemm_mma(const __nv_bfloat16* __restrict__ Ah,
           const __nv_bfloat16* __restrict__ Al,
           const __nv_bfloat16* __restrict__ Whi,
           const __nv_bfloat16* __restrict__ Wlo,
           float* __restrict__ C, int M)
{
    extern __shared__ __align__(16) char smem[];
    uint32_t sb = smem_to_u32(smem);

    int tid = threadIdx.x;
    int wid = tid >> 5, lane = tid & 31;
    int m0 = blockIdx.y * 128;
    int bn = blockIdx.x * 64;
    int warp_m = wid & 3;
    int warp_n = wid >> 2;

    float acc[2][4][4];
#pragma unroll
    for (int i = 0; i < 2; i++)
#pragma unroll
        for (int j = 0; j < 4; j++)
#pragma unroll
            for (int q = 0; q < 4; q++) acc[i][j][q] = 0.f;

    // ---- copy mappings ----
    // A: thread -> row tid/2, 32B half (tid&1); copies 2x16B for hi and lo
    int arow = tid >> 1, ahalf = tid & 1;
    int gra = m0 + arow; if (gra > M - 1) gra = M - 1;   // clamp (rows unused)
    const char* gAh = (const char*)(Ah + (size_t)gra * 256) + ahalf * 32;
    const char* gAl = (const char*)(Al + (size_t)gra * 256) + ahalf * 32;
    uint32_t sAoff = (uint32_t)arow * 80u + (uint32_t)ahalf * 32u;
    // W: thread -> n-row tid/4, 16B seg (tid&3); 1x16B for hi and lo
    int wr = tid >> 2, ws = tid & 3;
    const char* gWh = (const char*)(Whi + (size_t)(bn + wr) * 256) + ws * 16;
    const char* gWl = (const char*)(Wlo + (size_t)(bn + wr) * 256) + ws * 16;
    uint32_t sWoff = (uint32_t)wr * 80u + (uint32_t)ws * 16u;

    // ---- ldmatrix per-thread relative offsets ----
    uint32_t aRel[2], lRel[2];
#pragma unroll
    for (int i = 0; i < 2; i++) {
        uint32_t row = warp_m * 32 + i * 16 + (lane & 15);
        uint32_t col = ((lane >> 4) & 1) * 16;
        aRel[i] = ST_AH + row * 80 + col;
        lRel[i] = ST_AL + row * 80 + col;
    }
    uint32_t bRel[2], blRel[2];
#pragma unroll
    for (int p = 0; p < 2; p++) {
        uint32_t row = warp_n * 32 + p * 16 + (lane & 7) + ((lane >> 4) & 1) * 8;
        uint32_t col = ((lane >> 3) & 1) * 16;
        bRel[p]  = ST_WH + row * 80 + col;
        blRel[p] = ST_WL + row * 80 + col;
    }

    // chunk kc occupies bytes [kc*64, kc*64+64) of each 512B A row / W row
    auto issue = [&](int kc, int stg) {
        uint32_t base = sb + stg * STAGE_SZ;
        int gofs = kc * 64;
        CP_ASYNC16(base + ST_AH + sAoff,      gAh + gofs);
        CP_ASYNC16(base + ST_AH + sAoff + 16, gAh + gofs + 16);
        CP_ASYNC16(base + ST_AL + sAoff,      gAl + gofs);
        CP_ASYNC16(base + ST_AL + sAoff + 16, gAl + gofs + 16);
        CP_ASYNC16(base + ST_WH + sWoff,      gWh + gofs);
        CP_ASYNC16(base + ST_WL + sWoff,      gWl + gofs);
    };

    issue(0, 0);
    CP_COMMIT();

    for (int kc = 0; kc < 8; kc++) {
        int cur = kc & 1;
        if (kc < 7) {
            issue(kc + 1, cur ^ 1);
            CP_COMMIT();
            CP_WAIT1();
        } else {
            CP_WAIT0();
        }
        __syncthreads();

        uint32_t base = sb + cur * STAGE_SZ;
#pragma unroll
        for (int s = 0; s < 2; s++) {
            uint32_t ah[2][4], al[2][4];
            uint32_t wh[4][2], wl[4][2];
#pragma unroll
            for (int i = 0; i < 2; i++) {
                LDMX4(ah[i][0], ah[i][1], ah[i][2], ah[i][3], base + aRel[i] + s * 32);
                LDMX4(al[i][0], al[i][1], al[i][2], al[i][3], base + lRel[i] + s * 32);
            }
#pragma unroll
            for (int p = 0; p < 2; p++) {
                LDMX4(wh[2 * p][0], wh[2 * p][1], wh[2 * p + 1][0], wh[2 * p + 1][1],
                      base + bRel[p] + s * 32);
                LDMX4(wl[2 * p][0], wl[2 * p][1], wl[2 * p + 1][0], wl[2 * p + 1][1],
                      base + blRel[p] + s * 32);
            }
#pragma unroll
            for (int i = 0; i < 2; i++)
#pragma unroll
                for (int j = 0; j < 4; j++) {
                    MMA16816(acc[i][j], ah[i], wh[j]);
                    MMA16816(acc[i][j], ah[i], wl[j]);
                    MMA16816(acc[i][j], al[i], wh[j]);
                }
        }
        __syncthreads();
    }

    // ---- epilogue: stage 128x64 fp32 tile in smem (stride 68 floats) ----
    float* otile = (float*)smem;
#pragma unroll
    for (int i = 0; i < 2; i++)
#pragma unroll
        for (int j = 0; j < 4; j++) {
            int r0 = warp_m * 32 + i * 16 + (lane >> 2);
            int c0 = warp_n * 32 + j * 8 + (lane & 3) * 2;
            *(float2*)(otile + r0 * 68 + c0)       = make_float2(acc[i][j][0], acc[i][j][1]);
            *(float2*)(otile + (r0 + 8) * 68 + c0) = make_float2(acc[i][j][2], acc[i][j][3]);
        }
    __syncthreads();

#pragma unroll
    for (int it = 0; it < 8; it++) {
        int idx = tid + it * 256;
        int row = idx >> 4;
        int c4 = idx & 15;
        int gr = m0 + row;
        if (gr < M) {
            float4 v = *(float4*)(otile + row * 68 + c4 * 4);
            *(float4*)(C + (size_t)gr * NC + bn + c4 * 4) = v;
        }
    }
}

// ---------------------------------------------------------------------------
// Aggregation (unchanged, proven correct)
// ---------------------------------------------------------------------------
__global__ void k_agg256(const float* __restrict__ h, const float* __restrict__ bias,
                         float* __restrict__ out, int stats)
{
    int warp = threadIdx.x >> 5, lane = threadIdx.x & 31;
    int v = blockIdx.x * 8 + warp;

    float4 a0 = make_float4(0.f, 0.f, 0.f, 0.f);
    float4 a1 = make_float4(0.f, 0.f, 0.f, 0.f);

    int beg = g_rowptr[v], end = g_rowptr[v + 1];
    int nb = end - beg;
    for (int base = 0; base < nb; base += 32) {
        int rem = nb - base;
        int cnt = rem < 32 ? rem : 32;
        int idx = base + lane;
        int sl = (idx < nb) ? g_csrsrc[beg + idx] : 0;
        float wl = (idx < nb) ? g_dinv[sl] : 0.f;
        for (int j = 0; j < cnt; j++) {
            int   s = __shfl_sync(0xffffffffu, sl, j);
            float w = __shfl_sync(0xffffffffu, wl, j);
            const float4* rr = (const float4*)(h + (size_t)s * 256);
            float4 f0 = rr[lane], f1 = rr[lane + 32];
            a0.x += w * f0.x; a0.y += w * f0.y; a0.z += w * f0.z; a0.w += w * f0.w;
            a1.x += w * f1.x; a1.y += w * f1.y; a1.z += w * f1.z; a1.w += w * f1.w;
        }
    }
    float dv = g_dinv[v];
    {
        const float4* rr = (const float4*)(h + (size_t)v * 256);
        float4 f0 = rr[lane], f1 = rr[lane + 32];
        a0.x += dv * f0.x; a0.y += dv * f0.y; a0.z += dv * f0.z; a0.w += dv * f0.w;
        a1.x += dv * f1.x; a1.y += dv * f1.y; a1.z += dv * f1.z; a1.w += dv * f1.w;
    }
    const float4* bb = (const float4*)bias;
    float4 b0 = bb[lane], b1 = bb[lane + 32];
    float4 r0, r1;
    r0.x = a0.x * dv + b0.x; r0.y = a0.y * dv + b0.y;
    r0.z = a0.z * dv + b0.z; r0.w = a0.w * dv + b0.w;
    r1.x = a1.x * dv + b1.x; r1.y = a1.y * dv + b1.y;
    r1.z = a1.z * dv + b1.z; r1.w = a1.w * dv + b1.w;

    float4* op = (float4*)(out + (size_t)v * 256);
    op[lane] = r0; op[lane + 32] = r1;

    if (stats) {
        float lsum = r0.x + r0.y + r0.z + r0.w + r1.x + r1.y + r1.z + r1.w;
        float lsq  = r0.x*r0.x + r0.y*r0.y + r0.z*r0.z + r0.w*r0.w
                   + r1.x*r1.x + r1.y*r1.y + r1.z*r1.z + r1.w*r1.w;
#pragma unroll
        for (int off = 16; off > 0; off >>= 1) {
            lsum += __shfl_down_sync(0xffffffffu, lsum, off);
            lsq  += __shfl_down_sync(0xffffffffu, lsq,  off);
        }
        __shared__ float ss[8], sq[8];
        if (lane == 0) { ss[warp] = lsum; sq[warp] = lsq; }
        __syncthreads();
        if (threadIdx.x == 0) {
            float S = 0.f, Q = 0.f;
#pragma unroll
            for (int w = 0; w < 8; w++) { S += ss[w]; Q += sq[w]; }
            atomicAdd(&g_S[0], S);
            atomicAdd(&g_S[1], Q);
        }
    }
}

__global__ void k_agg128(const float* __restrict__ h, const float* __restrict__ bias,
                         float* __restrict__ out)
{
    int warp = threadIdx.x >> 5, lane = threadIdx.x & 31;
    int v = blockIdx.x * 8 + warp;

    float4 a0 = make_float4(0.f, 0.f, 0.f, 0.f);
    int beg = g_rowptr[v], end = g_rowptr[v + 1];
    int nb = end - beg;
    for (int base = 0; base < nb; base += 32) {
        int rem = nb - base;
        int cnt = rem < 32 ? rem : 32;
        int idx = base + lane;
        int sl = (idx < nb) ? g_csrsrc[beg + idx] : 0;
        float wl = (idx < nb) ? g_dinv[sl] : 0.f;
        for (int j = 0; j < cnt; j++) {
            int   s = __shfl_sync(0xffffffffu, sl, j);
            float w = __shfl_sync(0xffffffffu, wl, j);
            const float4* rr = (const float4*)(h + (size_t)s * 128);
            float4 f0 = rr[lane];
            a0.x += w * f0.x; a0.y += w * f0.y; a0.z += w * f0.z; a0.w += w * f0.w;
        }
    }
    float dv = g_dinv[v];
    {
        const float4* rr = (const float4*)(h + (size_t)v * 128);
        float4 f0 = rr[lane];
        a0.x += dv * f0.x; a0.y += dv * f0.y; a0.z += dv * f0.z; a0.w += dv * f0.w;
    }
    const float4* bb = (const float4*)bias;
    float4 b0 = bb[lane];
    float4 r0;
    r0.x = a0.x * dv + b0.x; r0.y = a0.y * dv + b0.y;
    r0.z = a0.z * dv + b0.z; r0.w = a0.w * dv + b0.w;
    ((float4*)(out + (size_t)v * 128))[lane] = r0;
}

// ---------------------------------------------------------------------------
// LayerNorm(graph)
// ---------------------------------------------------------------------------
__global__ void k_zeroS() { g_S[0] = 0.f; g_S[1] = 0.f; }

__global__ void k_lnfin() {
    float cnt = (float)NN * 256.0f;
    float mean = g_S[0] / cnt;
    float var  = g_S[1] / cnt - mean * mean;
    var = fmaxf(var, 0.f);
    g_prm[0] = mean;
    g_prm[1] = 1.0f / (sqrtf(var) + 1e-5f);
}

// y = lrelu((x-mean)*scale*gamma + beta), emitted directly as bf16 hi/lo
__global__ void k_apply(const float* __restrict__ buf,
                        const float* __restrict__ gma,
                        const float* __restrict__ bta,
                        __nv_bfloat16* __restrict__ ah,
                        __nv_bfloat16* __restrict__ al)
{
    int i4 = blockIdx.x * blockDim.x + threadIdx.x;  // NN*64 total
    float mean = g_prm[0], scale = g_prm[1];
    int c4 = i4 & 63;
    float4 g = ((const float4*)gma)[c4];
    float4 b = ((const float4*)bta)[c4];
    float4 v = ((const float4*)buf)[i4];
    v.x = (v.x - mean) * scale * g.x + b.x;
    v.y = (v.y - mean) * scale * g.y + b.y;
    v.z = (v.z - mean) * scale * g.z + b.z;
    v.w = (v.w - mean) * scale * g.w + b.w;
    v.x = v.x > 0.f ? v.x : 0.01f * v.x;
    v.y = v.y > 0.f ? v.y : 0.01f * v.y;
    v.z = v.z > 0.f ? v.z : 0.01f * v.z;
    v.w = v.w > 0.f ? v.w : 0.01f * v.w;
    uint2 hv, lv;
    split4(v, hv, lv);
    ((uint2*)ah)[i4] = hv;
    ((uint2*)al)[i4] = lv;
}

// ---------------------------------------------------------------------------
// Host launcher
// ---------------------------------------------------------------------------
extern "C" void kernel_launch(void* const* d_in, const int* in_sizes, int n_in,
                              void* d_out, int out_size)
{
    const float* x   = (const float*)d_in[0];
    const int*   ei  = (const int*)d_in[1];
    const int*   src = ei;
    const int*   dst = ei + NE;
    const float* W1 = (const float*)d_in[2];
    const float* b1 = (const float*)d_in[3];
    const float* g1 = (const float*)d_in[4];
    const float* e1 = (const float*)d_in[5];
    const float* W2 = (const float*)d_in[6];
    const float* b2 = (const float*)d_in[7];
    const float* g2 = (const float*)d_in[8];
    const float* e2 = (const float*)d_in[9];
    const float* W3 = (const float*)d_in[10];
    const float* b3 = (const float*)d_in[11];
    const float* g3 = (const float*)d_in[12];
    const float* e3 = (const float*)d_in[13];
    const float* W4 = (const float*)d_in[14];
    const float* b4 = (const float*)d_in[15];
    float* out = (float*)d_out;

    float *bufA = nullptr, *bufB = nullptr;
    cudaGetSymbolAddress((void**)&bufA, g_bufA);
    cudaGetSymbolAddress((void**)&bufB, g_bufB);
    __nv_bfloat16 *ah, *al;
    cudaGetSymbolAddress((void**)&ah, g_ah);
    cudaGetSymbolAddress((void**)&al, g_al);
    __nv_bfloat16 *w1h, *w1l, *w2h, *w2l, *w3h, *w3l, *w4h, *w4l;
    cudaGetSymbolAddress((void**)&w1h, g_w1h); cudaGetSymbolAddress((void**)&w1l, g_w1l);
    cudaGetSymbolAddress((void**)&w2h, g_w2h); cudaGetSymbolAddress((void**)&w2l, g_w2l);
    cudaGetSymbolAddress((void**)&w3h, g_w3h); cudaGetSymbolAddress((void**)&w3l, g_w3l);
    cudaGetSymbolAddress((void**)&w4h, g_w4h); cudaGetSymbolAddress((void**)&w4l, g_w4l);

    static bool attr_done = false;
    if (!attr_done) {
        cudaFuncSetAttribute(k_gemm_mma<256>, cudaFuncAttributeMaxDynamicSharedMemorySize, GEMM_SMEM);
        cudaFuncSetAttribute(k_gemm_mma<128>, cudaFuncAttributeMaxDynamicSharedMemorySize, GEMM_SMEM);
        attr_done = true;
    }

    const int T = 256;
    // ---- CSR build ----
    k_zero_counts<<<(NN + T - 1) / T, T>>>();
    k_degree<<<(NE + T - 1) / T, T>>>(dst);
    k_dinv<<<(NN + T - 1) / T, T>>>();
    k_scan1<<<NBLK, 1024>>>();
    k_scan2<<<1, 1>>>();
    k_scan3<<<(NN + T - 1) / T, T>>>();
    k_scatter<<<(NE + T - 1) / T, T>>>(src, dst);

    // ---- weight + input prep ----
    k_wprep<<<(256 * 256 + T - 1) / T, T>>>(W1, w1h, w1l, 256);
    k_wprep<<<(256 * 256 + T - 1) / T, T>>>(W2, w2h, w2l, 256);
    k_wprep<<<(256 * 256 + T - 1) / T, T>>>(W3, w3h, w3l, 256);
    k_wprep<<<(256 * 128 + T - 1) / T, T>>>(W4, w4h, w4l, 128);

    dim3 grid256(4, (NN + 127) / 128);    // x = n-block, y = m-block
    dim3 grid128(2, (NN + 127) / 128);
    int aggBlocks = NN / 8;               // 12500
    int vecBlocks = (NN * 64) / T;        // 25000 (NN*256/4 elements)

    k_xconv<<<vecBlocks, T>>>(x, ah, al);

    // ---- layer 1 ----
    k_gemm_mma<256><<<grid256, 256, GEMM_SMEM>>>(ah, al, w1h, w1l, bufA, NN);
    k_zeroS<<<1, 1>>>();
    k_agg256<<<aggBlocks, 256>>>(bufA, b1, bufB, 1);
    k_lnfin<<<1, 1>>>();
    k_apply<<<vecBlocks, T>>>(bufB, g1, e1, ah, al);

    // ---- layer 2 ----
    k_gemm_mma<256><<<grid256, 256, GEMM_SMEM>>>(ah, al, w2h, w2l, bufA, NN);
    k_zeroS<<<1, 1>>>();
    k_agg256<<<aggBlocks, 256>>>(bufA, b2, bufB, 1);
    k_lnfin<<<1, 1>>>();
    k_apply<<<vecBlocks, T>>>(bufB, g2, e2, ah, al);

    // ---- layer 3 ----
    k_gemm_mma<256><<<grid256, 256, GEMM_SMEM>>>(ah, al, w3h, w3l, bufA, NN);
    k_zeroS<<<1, 1>>>();
    k_agg256<<<aggBlocks, 256>>>(bufA, b3, bufB, 1);
    k_lnfin<<<1, 1>>>();
    k_apply<<<vecBlocks, T>>>(bufB, g3, e3, ah, al);

    // ---- layer 4 (D=128, no LN) ----
    k_gemm_mma<128><<<grid128, 256, GEMM_SMEM>>>(ah, al, w4h, w4l, bufA, NN);
    k_agg128<<<aggBlocks, 256>>>(bufA, b4, out);
}